// round 15
// baseline (speedup 1.0000x reference)
#include <cuda_runtime.h>
#include <cuda_bf16.h>
#include <math.h>
#include <cstdint>

#define B_  64
#define T_  256
#define D_  384
#define H_  6
#define HS_ 64
#define L_  6
#define V_  65
#define FF_ 1536
#define M_  (B_*T_)   // 16384 tokens

// ---------------- scratch (device globals; no allocation allowed) ----------------
__device__ float g_x[M_*D_];
__device__ float g_y[M_*D_];
__device__ float g_logits[M_*V_];
__device__ float g_losspart[2048];

__device__ __nv_bfloat16 g_qkvh[M_*3*D_], g_qkvl[M_*3*D_];
__device__ __nv_bfloat16 g_yh[M_*D_],  g_yl[M_*D_];
__device__ __nv_bfloat16 g_oh[M_*D_],  g_ol[M_*D_];
__device__ __nv_bfloat16 g_h1h[M_*FF_], g_h1l[M_*FF_];

__device__ __nv_bfloat16 g_wqkvh[L_*3*D_*D_],  g_wqkvl[L_*3*D_*D_];
__device__ __nv_bfloat16 g_wprojh[L_*D_*D_],   g_wprojl[L_*D_*D_];
__device__ __nv_bfloat16 g_w1h[L_*FF_*D_],     g_w1l[L_*FF_*D_];
__device__ __nv_bfloat16 g_w2h[L_*D_*FF_],     g_w2l[L_*D_*FF_];

// ---------------- helpers ----------------
static __device__ __forceinline__ uint32_t s2u(const void* p) {
    uint32_t a;
    asm("{ .reg .u64 t; cvta.to.shared.u64 t, %1; cvt.u32.u64 %0, t; }" : "=r"(a) : "l"(p));
    return a;
}
static __device__ __forceinline__ void split2(float v, __nv_bfloat16& hi, __nv_bfloat16& lo) {
    hi = __float2bfloat16(v);
    lo = __float2bfloat16(v - __bfloat162float(hi));
}
static __device__ __forceinline__ void ldmx4(uint32_t* r, uint32_t addr) {
    asm volatile("ldmatrix.sync.aligned.m8n8.x4.shared.b16 {%0,%1,%2,%3}, [%4];"
                 : "=r"(r[0]), "=r"(r[1]), "=r"(r[2]), "=r"(r[3]) : "r"(addr));
}
static __device__ __forceinline__ void ldmx4t(uint32_t* r, uint32_t addr) {
    asm volatile("ldmatrix.sync.aligned.m8n8.x4.trans.shared.b16 {%0,%1,%2,%3}, [%4];"
                 : "=r"(r[0]), "=r"(r[1]), "=r"(r[2]), "=r"(r[3]) : "r"(addr));
}
static __device__ __forceinline__ void mma16816(float* c, const uint32_t* a,
                                                uint32_t b0, uint32_t b1) {
    asm volatile(
        "mma.sync.aligned.m16n8k16.row.col.f32.bf16.bf16.f32 "
        "{%0,%1,%2,%3}, {%4,%5,%6,%7}, {%8,%9}, {%0,%1,%2,%3};"
        : "+f"(c[0]), "+f"(c[1]), "+f"(c[2]), "+f"(c[3])
        : "r"(a[0]), "r"(a[1]), "r"(a[2]), "r"(a[3]), "r"(b0), "r"(b1));
}
static __device__ __forceinline__ void cpasync16(uint32_t dst, const void* src) {
    asm volatile("cp.async.cg.shared.global [%0], [%1], 16;" :: "r"(dst), "l"(src) : "memory");
}
static __device__ __forceinline__ void pksplit(float a, float b, uint32_t& hi, uint32_t& lo) {
    __nv_bfloat16 ah, al, bh, bl;
    split2(a, ah, al);
    split2(b, bh, bl);
    __nv_bfloat16 hp[2] = {ah, bh}, lp[2] = {al, bl};
    hi = *(uint32_t*)hp;
    lo = *(uint32_t*)lp;
}

// ---------------- weight conversion ----------------
__global__ void convqkv_k(const float* __restrict__ Wq, const float* __restrict__ Wk,
                          const float* __restrict__ Wv,
                          __nv_bfloat16* __restrict__ oh, __nv_bfloat16* __restrict__ ol) {
    long i = (long)blockIdx.x * blockDim.x + threadIdx.x;
    const long total = (long)L_ * 3 * D_ * D_;
    if (i >= total) return;
    int k = (int)(i % D_);
    long t = i / D_;
    int n = (int)(t % (3 * D_));
    int l = (int)(t / (3 * D_));
    const float* W; int cc;
    if (n < D_)          { W = Wq; cc = n; }
    else if (n < 2 * D_) { W = Wk; cc = n - D_; }
    else                 { W = Wv; cc = n - 2 * D_; }
    int h = cc / HS_, e = cc % HS_;
    float v = W[(((long)l * H_ + h) * D_ + k) * HS_ + e];
    split2(v, oh[i], ol[i]);
}

__global__ void convt_k(const float* __restrict__ in,
                        __nv_bfloat16* __restrict__ oh, __nv_bfloat16* __restrict__ ol,
                        int Kd, int Nd) {
    long i = (long)blockIdx.x * blockDim.x + threadIdx.x;
    const long total = (long)L_ * Nd * Kd;
    if (i >= total) return;
    int k = (int)(i % Kd);
    long t = i / Kd;
    int n = (int)(t % Nd);
    int l = (int)(t / Nd);
    float v = in[((long)l * Kd + k) * Nd + n];
    split2(v, oh[i], ol[i]);
}

// ---------------- embedding ----------------
__global__ void embed_k(const int* __restrict__ idx, const float* __restrict__ tok,
                        const float* __restrict__ pos, float* __restrict__ x) {
    int i = blockIdx.x * blockDim.x + threadIdx.x;
    if (i >= M_ * D_) return;
    int d = i % D_;
    int r = i / D_;
    int t = r % T_;
    x[i] = tok[(long)idx[r] * D_ + d] + pos[(long)t * D_ + d];
}

// ---------------- layernorm: warp per row ----------------
__global__ void ln_k(const float* __restrict__ x, float* __restrict__ y,
                     __nv_bfloat16* __restrict__ yh, __nv_bfloat16* __restrict__ yl,
                     const float* __restrict__ g, const float* __restrict__ b) {
    int row = blockIdx.x * 8 + (threadIdx.x >> 5);
    int lane = threadIdx.x & 31;
    const float* xr = x + (long)row * D_;
    float v[12];
    float s = 0.f, s2 = 0.f;
    #pragma unroll
    for (int i = 0; i < 12; i++) {
        v[i] = xr[lane + i * 32];
        s += v[i]; s2 += v[i] * v[i];
    }
    #pragma unroll
    for (int o = 16; o; o >>= 1) {
        s  += __shfl_xor_sync(0xffffffffu, s,  o);
        s2 += __shfl_xor_sync(0xffffffffu, s2, o);
    }
    float mean = s * (1.f / D_);
    float var  = s2 * (1.f / D_) - mean * mean;
    float inv  = rsqrtf(var + 1e-5f);
    #pragma unroll
    for (int i = 0; i < 12; i++) {
        int d = lane + i * 32;
        float o = (v[i] - mean) * inv * g[d] + b[d];
        if (y) y[(long)row * D_ + d] = o;
        if (yh) split2(o, yh[(long)row * D_ + d], yl[(long)row * D_ + d]);
    }
}

// ---------------- mma.sync split-bf16 GEMM (templated on BM) ----------------
// BM x 128 CTA tile, 128 threads, warp grid 2x2, warp tile (BM/2)x64.
// K chunks of 32, cp.async double buffer, smem stride 40 bf16.
#define GSTRIDE 40
template<int BM>
__global__ void __launch_bounds__(128)
gemm_bf16_k(const __nv_bfloat16* __restrict__ Ah, const __nv_bfloat16* __restrict__ Al,
            const __nv_bfloat16* __restrict__ Bh, const __nv_bfloat16* __restrict__ Bl,
            const float* __restrict__ bias, const float* __restrict__ Cin,
            float* __restrict__ C,
            __nv_bfloat16* __restrict__ Oh, __nv_bfloat16* __restrict__ Ol,
            int N, int K, int relu) {
    constexpr int MF = BM / 32;              // 16-row frags per warp (BM=128 -> 4, 64 -> 2)
    constexpr int AT = BM * GSTRIDE;         // A tile elems
    constexpr int BT = 128 * GSTRIDE;        // B tile elems
    constexpr int BUF = 2 * AT + 2 * BT;     // elems per stage
    extern __shared__ __align__(16) char smem[];
    uint32_t sb = s2u(smem);
    int tid = threadIdx.x, wid = tid >> 5, lane = tid & 31;
    int wm = wid >> 1, wn = wid & 1;
    int m0 = blockIdx.y * BM, n0 = blockIdx.x * 128;

    float acc[MF][8][4];
    #pragma unroll
    for (int i = 0; i < MF; i++)
        #pragma unroll
        for (int j = 0; j < 8; j++)
            #pragma unroll
            for (int q = 0; q < 4; q++) acc[i][j][q] = 0.f;

    int sel  = lane >> 3;
    int arow = (lane & 7) + ((sel & 1) << 3);
    int acol = (sel >> 1) << 3;
    int brow = (lane & 7) + ((sel >> 1) << 3);
    int bcol = (sel & 1) << 3;

    const int nch = K >> 5;

    #define ISSUE(ch, buf) do { \
        int kc = (ch) * 32; \
        const __nv_bfloat16* srcs[4] = {Ah, Al, Bh, Bl}; \
        const int offs[4] = {0, AT, 2 * AT, 2 * AT + BT}; \
        _Pragma("unroll") \
        for (int tt = 0; tt < 4; tt++) { \
            const __nv_bfloat16* sp = srcs[tt]; \
            int rb = (tt < 2) ? m0 : n0; \
            int rows = (tt < 2) ? BM : 128; \
            uint32_t db = sb + ((buf) * BUF + offs[tt]) * 2; \
            _Pragma("unroll") \
            for (int i = tid; i < rows * 4; i += 128) { \
                int r = i >> 2, c = (i & 3) * 8; \
                cpasync16(db + (r * GSTRIDE + c) * 2, sp + (long)(rb + r) * K + kc + c); \
            } \
        } \
        asm volatile("cp.async.commit_group;" ::: "memory"); \
    } while (0)

    ISSUE(0, 0);

    for (int ch = 0; ch < nch; ch++) {
        if (ch + 1 < nch) {
            ISSUE(ch + 1, (ch + 1) & 1);
            asm volatile("cp.async.wait_group 1;" ::: "memory");
        } else {
            asm volatile("cp.async.wait_group 0;" ::: "memory");
        }
        __syncthreads();

        uint32_t base = sb + ((ch & 1) * BUF) * 2;
        uint32_t tAh = base;
        uint32_t tAl = base + AT * 2;
        uint32_t tBh = base + 2 * AT * 2;
        uint32_t tBl = base + (2 * AT + BT) * 2;

        #pragma unroll
        for (int ks = 0; ks < 2; ks++) {
            int k0 = ks * 16;
            uint32_t ahf[MF][4], alf[MF][4];
            #pragma unroll
            for (int mf = 0; mf < MF; mf++) {
                uint32_t off = ((wm * (BM / 2) + mf * 16 + arow) * GSTRIDE + k0 + acol) * 2;
                ldmx4(ahf[mf], tAh + off);
                ldmx4(alf[mf], tAl + off);
            }
            uint32_t bhf[4][4], blf[4][4];
            #pragma unroll
            for (int ng = 0; ng < 4; ng++) {
                uint32_t off = ((wn * 64 + ng * 16 + brow) * GSTRIDE + k0 + bcol) * 2;
                ldmx4(bhf[ng], tBh + off);
                ldmx4(blf[ng], tBl + off);
            }
            #pragma unroll
            for (int mf = 0; mf < MF; mf++) {
                #pragma unroll
                for (int ng = 0; ng < 4; ng++) {
                    mma16816(acc[mf][ng * 2],     ahf[mf], bhf[ng][0], bhf[ng][1]);
                    mma16816(acc[mf][ng * 2 + 1], ahf[mf], bhf[ng][2], bhf[ng][3]);
                    mma16816(acc[mf][ng * 2],     ahf[mf], blf[ng][0], blf[ng][1]);
                    mma16816(acc[mf][ng * 2 + 1], ahf[mf], blf[ng][2], blf[ng][3]);
                    mma16816(acc[mf][ng * 2],     alf[mf], bhf[ng][0], bhf[ng][1]);
                    mma16816(acc[mf][ng * 2 + 1], alf[mf], bhf[ng][2], bhf[ng][3]);
                }
            }
        }
        __syncthreads();
    }

    int tr = lane >> 2, tc = (lane & 3) * 2;
    #pragma unroll
    for (int mf = 0; mf < MF; mf++) {
        #pragma unroll
        for (int half = 0; half < 2; half++) {
            long row = m0 + wm * (BM / 2) + mf * 16 + tr + half * 8;
            #pragma unroll
            for (int nf = 0; nf < 8; nf++) {
                int col = n0 + wn * 64 + nf * 8 + tc;
                float v0 = acc[mf][nf][half * 2 + 0];
                float v1 = acc[mf][nf][half * 2 + 1];
                if (bias) { v0 += bias[col]; v1 += bias[col + 1]; }
                if (Cin) {
                    float2 ci = *(const float2*)(Cin + row * (long)N + col);
                    v0 += ci.x; v1 += ci.y;
                }
                if (relu) { v0 = fmaxf(v0, 0.f); v1 = fmaxf(v1, 0.f); }
                if (C) *(float2*)(C + row * (long)N + col) = make_float2(v0, v1);
                if (Oh) {
                    uint32_t hp, lp;
                    pksplit(v0, v1, hp, lp);
                    *(uint32_t*)(Oh + row * (long)N + col) = hp;
                    *(uint32_t*)(Ol + row * (long)N + col) = lp;
                }
            }
        }
    }
}

// ---------------- small-N fp32 GEMM (head, N=65) ----------------
__global__ void gemm_k(const float* __restrict__ A, const float* __restrict__ Bw,
                       const float* __restrict__ bias, float* __restrict__ C,
                       int N, int K) {
    __shared__ float As[8][128];
    __shared__ float Bs[8][128];
    int tid = threadIdx.x;
    int m0 = blockIdx.y * 128, n0 = blockIdx.x * 128;
    int arow = tid >> 1, ac4 = (tid & 1) * 4;
    int brow = tid >> 5, bcol = (tid & 31) * 4;
    int ty = tid >> 4, tx = tid & 15;

    float acc[8][8];
    #pragma unroll
    for (int i = 0; i < 8; i++)
        #pragma unroll
        for (int j = 0; j < 8; j++) acc[i][j] = 0.f;

    const float* Aptr = A + (long)(m0 + arow) * K + ac4;

    for (int kt = 0; kt < K; kt += 8) {
        float4 av = *(const float4*)(Aptr + kt);
        As[ac4 + 0][arow] = av.x; As[ac4 + 1][arow] = av.y;
        As[ac4 + 2][arow] = av.z; As[ac4 + 3][arow] = av.w;

        int col = n0 + bcol;
        const float* bp = Bw + (long)(kt + brow) * N;
        float4 bv;
        bv.x = (col + 0 < N) ? bp[col + 0] : 0.f;
        bv.y = (col + 1 < N) ? bp[col + 1] : 0.f;
        bv.z = (col + 2 < N) ? bp[col + 2] : 0.f;
        bv.w = (col + 3 < N) ? bp[col + 3] : 0.f;
        *(float4*)&Bs[brow][bcol] = bv;
        __syncthreads();

        #pragma unroll
        for (int kk = 0; kk < 8; kk++) {
            float a[8], bb[8];
            *(float4*)&a[0]  = *(const float4*)&As[kk][ty * 8];
            *(float4*)&a[4]  = *(const float4*)&As[kk][ty * 8 + 4];
            *(float4*)&bb[0] = *(const float4*)&Bs[kk][tx * 8];
            *(float4*)&bb[4] = *(const float4*)&Bs[kk][tx * 8 + 4];
            #pragma unroll
            for (int i = 0; i < 8; i++)
                #pragma unroll
                for (int j = 0; j < 8; j++) acc[i][j] += a[i] * bb[j];
        }
        __syncthreads();
    }

    #pragma unroll
    for (int i = 0; i < 8; i++) {
        long row = m0 + ty * 8 + i;
        float* crow = C + row * (long)N;
        #pragma unroll
        for (int j = 0; j < 8; j++) {
            int col = n0 + tx * 8 + j;
            if (col < N) crow[col] = acc[i][j] + (bias ? bias[col] : 0.f);
        }
    }
}

// ---------------- tensor-core flash attention, 64-key chunks ----------------
// grid (bh, qblock). 8 warps; warp owns 16 q-rows; keys iterate in 64-chunks
// (halves score regs + K/V smem vs 128: smem 74KB, launch_bounds(256,2)).
#define ASTRIDE 72
#define AQTILE  (128*ASTRIDE)   // Q tile elems (128 rows)
#define AKTILE  (64*ASTRIDE)    // K/V tile elems (64 rows)
__global__ void __launch_bounds__(256, 2)
fattn_k(const __nv_bfloat16* __restrict__ qkvh, const __nv_bfloat16* __restrict__ qkvl,
        __nv_bfloat16* __restrict__ oh, __nv_bfloat16* __restrict__ ol) {
    extern __shared__ __align__(16) char sma[];
    uint32_t sb = s2u(sma);
    __nv_bfloat16* tiles = (__nv_bfloat16*)sma;
    // layout: Qh[128] Ql[128] Kh[64] Kl[64] Vh[64] Vl[64]  (rows x ASTRIDE)
    const uint32_t oQh = 0, oQl = AQTILE, oKh = 2 * AQTILE, oKl = 2 * AQTILE + AKTILE,
                   oVh = 2 * AQTILE + 2 * AKTILE, oVl = 2 * AQTILE + 3 * AKTILE;

    int bh = blockIdx.x;
    int b = bh / H_, h = bh % H_;
    int qb = blockIdx.y;
    int tid = threadIdx.x, wid = tid >> 5, lane = tid & 31;
    const __nv_bfloat16* baseh = qkvh + (long)b * T_ * 3 * D_;
    const __nv_bfloat16* basel = qkvl + (long)b * T_ * 3 * D_;
    const float scale = 0.05103103630798288f;  // 384^-0.5

    // copy ROWS rows x 64 bf16 from (trow0, coloff) into tiles at elem-offset dsth/dstl
    #define LOADBF(ROWS, trow0, coloff, dsth, dstl) do { \
        _Pragma("unroll") \
        for (int it = 0; it < (ROWS) / 32; it++) { \
            int id = tid + it * 256; \
            int r = id >> 3, c8 = (id & 7) * 8; \
            long src = (long)((trow0) + r) * (3 * D_) + (coloff) + c8; \
            *(uint4*)(tiles + (dsth) + r * ASTRIDE + c8) = *(const uint4*)(baseh + src); \
            *(uint4*)(tiles + (dstl) + r * ASTRIDE + c8) = *(const uint4*)(basel + src); \
        } \
    } while (0)

    LOADBF(128, qb * 128, h * HS_, oQh, oQl);
    LOADBF(64, 0, D_ + h * HS_, oKh, oKl);
    LOADBF(64, 0, 2 * D_ + h * HS_, oVh, oVl);
    __syncthreads();

    int sel  = lane >> 3;
    int arow = (lane & 7) + ((sel & 1) << 3);
    int acol = (sel >> 1) << 3;
    int brow = (lane & 7) + ((sel >> 1) << 3);
    int bcol = (sel & 1) << 3;
    int vrow = (lane & 7) + (((lane >> 3) & 1) << 3);
    int vcol = ((lane >> 4) & 1) << 3;

    uint32_t qfh[4][4], qfl[4][4];
    #pragma unroll
    for (int ks = 0; ks < 4; ks++) {
        uint32_t off = ((wid * 16 + arow) * ASTRIDE + ks * 16 + acol) * 2;
        ldmx4(qfh[ks], sb + oQh * 2 + off);
        ldmx4(qfl[ks], sb + oQl * 2 + off);
    }

    float So[8][4];
    #pragma unroll
    for (int a = 0; a < 8; a++)
        #pragma unroll
        for (int j = 0; j < 4; j++) So[a][j] = 0.f;
    float mrow0 = -1e30f, mrow1 = -1e30f, lrow0 = 0.f, lrow1 = 0.f;

    const int rg0 = qb * 128 + wid * 16 + (lane >> 2);
    const int ccol = (lane & 3) * 2;
    const int nch = 2 * (qb + 1);   // 64-key chunks covering keys <= q-block end

    for (int ch = 0; ch < nch; ch++) {
        if (ch) {
            __syncthreads();
            LOADBF(64, ch * 64, D_ + h * HS_, oKh, oKl);
            LOADBF(64, ch * 64, 2 * D_ + h * HS_, oVh, oVl);
            __syncthreads();
        }
        // ---- S = Q K^T (3 passes), 64 keys ----
        float sa[8][4];
        #pragma unroll
        for (int ni = 0; ni < 8; ni++)
            #pragma unroll
            for (int j = 0; j < 4; j++) sa[ni][j] = 0.f;
        #pragma unroll
        for (int ks = 0; ks < 4; ks++) {
            #pragma unroll
            for (int ng = 0; ng < 4; ng++) {
                uint32_t off = ((ng * 16 + brow) * ASTRIDE + ks * 16 + bcol) * 2;
                uint32_t kh4[4], kl4[4];
                ldmx4(kh4, sb + oKh * 2 + off);
                ldmx4(kl4, sb + oKl * 2 + off);
                mma16816(sa[ng * 2],     qfh[ks], kh4[0], kh4[1]);
                mma16816(sa[ng * 2 + 1], qfh[ks], kh4[2], kh4[3]);
                mma16816(sa[ng * 2],     qfh[ks], kl4[0], kl4[1]);
                mma16816(sa[ng * 2 + 1], qfh[ks], kl4[2], kl4[3]);
                mma16816(sa[ng * 2],     qfl[ks], kh4[0], kh4[1]);
                mma16816(sa[ng * 2 + 1], qfl[ks], kh4[2], kh4[3]);
            }
        }
        // ---- scale + causal mask (mask only on chunks overlapping the diagonal) ----
        bool diag = (ch * 64 + 63 > qb * 128 + wid * 16 + 15) || true;
        #pragma unroll
        for (int ni = 0; ni < 8; ni++) {
            #pragma unroll
            for (int j = 0; j < 4; j++) {
                float s = sa[ni][j] * scale;
                int key = ch * 64 + ni * 8 + ccol + (j & 1);
                int qr  = rg0 + ((j >> 1) << 3);
                if (key > qr) s = -1e30f;
                sa[ni][j] = s;
            }
        }
        (void)diag;
        // ---- online softmax ----
        float mx0 = -1e30f, mx1 = -1e30f;
        #pragma unroll
        for (int ni = 0; ni < 8; ni++) {
            mx0 = fmaxf(mx0, fmaxf(sa[ni][0], sa[ni][1]));
            mx1 = fmaxf(mx1, fmaxf(sa[ni][2], sa[ni][3]));
        }
        mx0 = fmaxf(mx0, __shfl_xor_sync(0xffffffffu, mx0, 1));
        mx0 = fmaxf(mx0, __shfl_xor_sync(0xffffffffu, mx0, 2));
        mx1 = fmaxf(mx1, __shfl_xor_sync(0xffffffffu, mx1, 1));
        mx1 = fmaxf(mx1, __shfl_xor_sync(0xffffffffu, mx1, 2));
        float mn0 = fmaxf(mrow0, mx0), mn1 = fmaxf(mrow1, mx1);
        float c0 = __expf(mrow0 - mn0), c1 = __expf(mrow1 - mn1);
        mrow0 = mn0; mrow1 = mn1;
        float s0 = 0.f, s1 = 0.f;
        #pragma unroll
        for (int ni = 0; ni < 8; ni++) {
            sa[ni][0] = __expf(sa[ni][0] - mn0);
            sa[ni][1] = __expf(sa[ni][1] - mn0);
            sa[ni][2] = __expf(sa[ni][2] - mn1);
            sa[ni][3] = __expf(sa[ni][3] - mn1);
            s0 += sa[ni][0] + sa[ni][1];
            s1 += sa[ni][2] + sa[ni][3];
        }
        s0 += __shfl_xor_sync(0xffffffffu, s0, 1);
        s0 += __shfl_xor_sync(0xffffffffu, s0, 2);
        s1 += __shfl_xor_sync(0xffffffffu, s1, 1);
        s1 += __shfl_xor_sync(0xffffffffu, s1, 2);
        lrow0 = lrow0 * c0 + s0;
        lrow1 = lrow1 * c1 + s1;
        #pragma unroll
        for (int a = 0; a < 8; a++) {
            So[a][0] *= c0; So[a][1] *= c0;
            So[a][2] *= c1; So[a][3] *= c1;
        }
        // ---- O += P * V (split P, 3 passes), 64 keys = 4 k-steps ----
        #pragma unroll
        for (int ks = 0; ks < 4; ks++) {
            uint32_t pfh[4], pfl[4];
            pksplit(sa[2 * ks][0],     sa[2 * ks][1],     pfh[0], pfl[0]);
            pksplit(sa[2 * ks][2],     sa[2 * ks][3],     pfh[1], pfl[1]);
            pksplit(sa[2 * ks + 1][0], sa[2 * ks + 1][1], pfh[2], pfl[2]);
            pksplit(sa[2 * ks + 1][2], sa[2 * ks + 1][3], pfh[3], pfl[3]);
            #pragma unroll
            for (int np = 0; np < 4; np++) {
                uint32_t voff = ((ks * 16 + vrow) * ASTRIDE + np * 16 + vcol) * 2;
                uint32_t vh4[4], vl4[4];
                ldmx4t(vh4, sb + oVh * 2 + voff);
                ldmx4t(vl4, sb + oVl * 2 + voff);
                mma16816(So[np * 2],     pfh, vh4[0], vh4[1]);
                mma16816(So[np * 2 + 1], pfh, vh4[2], vh4[3]);
                mma16816(So[np * 2],     pfh, vl4[0], vl4[1]);
                mma16816(So[np * 2 + 1], pfh, vl4[2], vl4[3]);
                mma16816(So[np * 2],     pfl, vh4[0], vh4[1]);
                mma16816(So[np * 2 + 1], pfl, vh4[2], vh4[3]);
            }
        }
    }

    // ---- write output (split bf16) ----
    float rl0 = 1.f / lrow0, rl1 = 1.f / lrow1;
    #pragma unroll
    for (int a = 0; a < 8; a++) {
        int col = h * HS_ + a * 8 + ccol;
        long row0 = (long)b * T_ + rg0;
        long row1 = row0 + 8;
        uint32_t hp, lp;
        pksplit(So[a][0] * rl0, So[a][1] * rl0, hp, lp);
        *(uint32_t*)(oh + row0 * D_ + col) = hp;
        *(uint32_t*)(ol + row0 * D_ + col) = lp;
        pksplit(So[a][2] * rl1, So[a][3] * rl1, hp, lp);
        *(uint32_t*)(oh + row1 * D_ + col) = hp;
        *(uint32_t*)(ol + row1 * D_ + col) = lp;
    }
}

// ---------------- loss ----------------
__global__ void loss_k(const float* __restrict__ logits, const int* __restrict__ targets,
                       float* __restrict__ part) {
    int gwarp = (blockIdx.x * blockDim.x + threadIdx.x) >> 5;
    int lane = threadIdx.x & 31;
    const float* lr = logits + (long)gwarp * V_;
    float mx = -1e30f;
    for (int c = lane; c < V_; c += 32) mx = fmaxf(mx, lr[c]);
    #pragma unroll
    for (int o = 16; o; o >>= 1) mx = fmaxf(mx, __shfl_xor_sync(0xffffffffu, mx, o));
    float se = 0.f;
    for (int c = lane; c < V_; c += 32) se += expf(lr[c] - mx);
    #pragma unroll
    for (int o = 16; o; o >>= 1) se += __shfl_xor_sync(0xffffffffu, se, o);
    float li = (mx + logf(se)) - lr[targets[gwarp]];
    __shared__ float ws[8];
    if (lane == 0) ws[threadIdx.x >> 5] = li;
    __syncthreads();
    if (threadIdx.x == 0) {
        float s = 0.f;
        #pragma unroll
        for (int i = 0; i < 8; i++) s += ws[i];
        part[blockIdx.x] = s;
    }
}

__global__ void finalize_k(float* out, long out_size, const float* __restrict__ part) {
    float v = 0.f;
    for (int i = threadIdx.x; i < 2048; i += 256) v += part[i];
    #pragma unroll
    for (int o = 16; o; o >>= 1) v += __shfl_xor_sync(0xffffffffu, v, o);
    __shared__ float sm[8];
    if ((threadIdx.x & 31) == 0) sm[threadIdx.x >> 5] = v;
    __syncthreads();
    if (threadIdx.x == 0) {
        float s = 0.f;
        #pragma unroll
        for (int i = 0; i < 8; i++) s += sm[i];
        float loss = s / (float)M_;
        const long btv = (long)M_ * V_;
        if (out_size > btv)       out[btv] = loss;
        else if (out_size == 1)   out[0]   = loss;
    }
}

// ---------------- driver ----------------
extern "C" void kernel_launch(void* const* d_in, const int* in_sizes, int n_in,
                              void* d_out, int out_size) {
    const int*   idx     = (const int*)d_in[0];
    const int*   targets = (const int*)d_in[1];
    const float* tok     = (const float*)d_in[2];
    const float* pos     = (const float*)d_in[3];
    const float* Wq      = (const float*)d_in[4];
    const float* Wk      = (const float*)d_in[5];
    const float* Wv      = (const float*)d_in[6];
    const float* Wproj   = (const float*)d_in[7];
    const float* bproj   = (const float*)d_in[8];
    const float* W1      = (const float*)d_in[9];
    const float* b1      = (const float*)d_in[10];
    const float* W2      = (const float*)d_in[11];
    const float* b2      = (const float*)d_in[12];
    const float* ln1g    = (const float*)d_in[13];
    const float* ln1b    = (const float*)d_in[14];
    const float* lnfg    = (const float*)d_in[15];
    const float* lnfb    = (const float*)d_in[16];
    const float* Whead   = (const float*)d_in[17];
    const float* bhead   = (const float*)d_in[18];
    float* out = (float*)d_out;

    float *x, *y, *lgts, *part;
    __nv_bfloat16 *qkvh, *qkvl, *yh, *yl, *oh, *ol, *h1h, *h1l;
    __nv_bfloat16 *wqh, *wql, *wph, *wpl, *w1h, *w1l, *w2h, *w2l;
    cudaGetSymbolAddress((void**)&x,    g_x);
    cudaGetSymbolAddress((void**)&y,    g_y);
    cudaGetSymbolAddress((void**)&lgts, g_logits);
    cudaGetSymbolAddress((void**)&part, g_losspart);
    cudaGetSymbolAddress((void**)&qkvh, g_qkvh);
    cudaGetSymbolAddress((void**)&qkvl, g_qkvl);
    cudaGetSymbolAddress((void**)&yh,   g_yh);
    cudaGetSymbolAddress((void**)&yl,   g_yl);
    cudaGetSymbolAddress((void**)&oh,   g_oh);
    cudaGetSymbolAddress((void**)&ol,   g_ol);
    cudaGetSymbolAddress((void**)&h1h,  g_h1h);
    cudaGetSymbolAddress((void**)&h1l,  g_h1l);
    cudaGetSymbolAddress((void**)&wqh,  g_wqkvh);
    cudaGetSymbolAddress((void**)&wql,  g_wqkvl);
    cudaGetSymbolAddress((void**)&wph,  g_wprojh);
    cudaGetSymbolAddress((void**)&wpl,  g_wprojl);
    cudaGetSymbolAddress((void**)&w1h,  g_w1h);
    cudaGetSymbolAddress((void**)&w1l,  g_w1l);
    cudaGetSymbolAddress((void**)&w2h,  g_w2h);
    cudaGetSymbolAddress((void**)&w2l,  g_w2l);

    const int attn_smem = (2 * AQTILE + 4 * AKTILE) * 2;   // 73728 B
    cudaFuncSetAttribute(fattn_k, cudaFuncAttributeMaxDynamicSharedMemorySize, attn_smem);
    const int gsmem128 = 2 * (2 * 128 * GSTRIDE + 2 * 128 * GSTRIDE) * 2;  // 81920
    const int gsmem64  = 2 * (2 * 64 * GSTRIDE + 2 * 128 * GSTRIDE) * 2;   // 61440
    cudaFuncSetAttribute(gemm_bf16_k<128>, cudaFuncAttributeMaxDynamicSharedMemorySize, gsmem128);
    cudaFuncSetAttribute(gemm_bf16_k<64>,  cudaFuncAttributeMaxDynamicSharedMemorySize, gsmem64);

    const long btv = (long)M_ * V_;
    float* logits = ((long)out_size >= btv) ? out : lgts;

    {
        long tq = (long)L_ * 3 * D_ * D_;
        convqkv_k<<<(int)((tq + 255) / 256), 256>>>(Wq, Wk, Wv, wqh, wql);
        long tp = (long)L_ * D_ * D_;
        convt_k<<<(int)((tp + 255) / 256), 256>>>(Wproj, wph, wpl, D_, D_);
        long t1 = (long)L_ * FF_ * D_;
        convt_k<<<(int)((t1 + 255) / 256), 256>>>(W1, w1h, w1l, D_, FF_);
        long t2 = (long)L_ * D_ * FF_;
        convt_k<<<(int)((t2 + 255) / 256), 256>>>(W2, w2h, w2l, FF_, D_);
    }
    embed_k<<<(M_ * D_ + 255) / 256, 256>>>(idx, tok, pos, x);

    for (int l = 0; l < L_; l++) {
        ln_k<<<M_ / 8, 256>>>(x, (float*)0, yh, yl, ln1g + (long)l * D_, ln1b + (long)l * D_);
        { dim3 g(9, 128);
          gemm_bf16_k<128><<<g, 128, gsmem128>>>(yh, yl,
              wqh + (long)l * 3 * D_ * D_, wql + (long)l * 3 * D_ * D_,
              (const float*)0, (const float*)0, (float*)0,
              qkvh, qkvl, 3 * D_, D_, 0); }
        { dim3 ga(B_ * H_, 2);
          fattn_k<<<ga, 256, attn_smem>>>(qkvh, qkvl, oh, ol); }
        { dim3 g(3, 256);
          gemm_bf16_k<64><<<g, 128, gsmem64>>>(oh, ol,
              wph + (long)l * D_ * D_, wpl + (long)l * D_ * D_,
              bproj + (long)l * D_, x, x,
              (__nv_bfloat16*)0, (__nv_bfloat16*)0, D_, D_, 0); }
        ln_k<<<M_ / 8, 256>>>(x, (float*)0, yh, yl, ln1g + (long)l * D_, ln1b + (long)l * D_);
        { dim3 g(12, 128);
          gemm_bf16_k<128><<<g, 128, gsmem128>>>(yh, yl,
              w1h + (long)l * FF_ * D_, w1l + (long)l * FF_ * D_,
              b1 + (long)l * FF_, (const float*)0, (float*)0,
              h1h, h1l, FF_, D_, 1); }
        { dim3 g(3, 256);
          gemm_bf16_k<64><<<g, 128, gsmem64>>>(h1h, h1l,
              w2h + (long)l * D_ * FF_, w2l + (long)l * D_ * FF_,
              b2 + (long)l * D_, x, x,
              (__nv_bfloat16*)0, (__nv_bfloat16*)0, D_, FF_, 0); }
    }

    ln_k<<<M_ / 8, 256>>>(x, y, (__nv_bfloat16*)0, (__nv_bfloat16*)0, lnfg, lnfb);
    { dim3 g(1, 128); gemm_k<<<g, 256>>>(y, Whead, bhead, logits, V_, D_); }
    loss_k<<<2048, 256>>>(logits, targets, part);
    finalize_k<<<1, 256>>>(out, (long)out_size, part);
}

// round 17
// speedup vs baseline: 1.0144x; 1.0144x over previous
#include <cuda_runtime.h>
#include <cuda_bf16.h>
#include <math.h>
#include <cstdint>

#define B_  64
#define T_  256
#define D_  384
#define H_  6
#define HS_ 64
#define L_  6
#define V_  65
#define FF_ 1536
#define M_  (B_*T_)   // 16384 tokens

// ---------------- scratch (device globals; no allocation allowed) ----------------
__device__ float g_x[M_*D_];
__device__ float g_y[M_*D_];
__device__ float g_logits[M_*V_];
__device__ float g_losspart[2048];

__device__ __nv_bfloat16 g_qkvh[M_*3*D_], g_qkvl[M_*3*D_];
__device__ __nv_bfloat16 g_yh[M_*D_],  g_yl[M_*D_];
__device__ __nv_bfloat16 g_oh[M_*D_],  g_ol[M_*D_];
__device__ __nv_bfloat16 g_h1h[M_*FF_], g_h1l[M_*FF_];

__device__ __nv_bfloat16 g_wqkvh[L_*3*D_*D_],  g_wqkvl[L_*3*D_*D_];
__device__ __nv_bfloat16 g_wprojh[L_*D_*D_],   g_wprojl[L_*D_*D_];
__device__ __nv_bfloat16 g_w1h[L_*FF_*D_],     g_w1l[L_*FF_*D_];
__device__ __nv_bfloat16 g_w2h[L_*D_*FF_],     g_w2l[L_*D_*FF_];

// ---------------- helpers ----------------
static __device__ __forceinline__ uint32_t s2u(const void* p) {
    uint32_t a;
    asm("{ .reg .u64 t; cvta.to.shared.u64 t, %1; cvt.u32.u64 %0, t; }" : "=r"(a) : "l"(p));
    return a;
}
static __device__ __forceinline__ void split2(float v, __nv_bfloat16& hi, __nv_bfloat16& lo) {
    hi = __float2bfloat16(v);
    lo = __float2bfloat16(v - __bfloat162float(hi));
}
static __device__ __forceinline__ void ldmx4(uint32_t* r, uint32_t addr) {
    asm volatile("ldmatrix.sync.aligned.m8n8.x4.shared.b16 {%0,%1,%2,%3}, [%4];"
                 : "=r"(r[0]), "=r"(r[1]), "=r"(r[2]), "=r"(r[3]) : "r"(addr));
}
static __device__ __forceinline__ void ldmx4t(uint32_t* r, uint32_t addr) {
    asm volatile("ldmatrix.sync.aligned.m8n8.x4.trans.shared.b16 {%0,%1,%2,%3}, [%4];"
                 : "=r"(r[0]), "=r"(r[1]), "=r"(r[2]), "=r"(r[3]) : "r"(addr));
}
static __device__ __forceinline__ void mma16816(float* c, const uint32_t* a,
                                                uint32_t b0, uint32_t b1) {
    asm volatile(
        "mma.sync.aligned.m16n8k16.row.col.f32.bf16.bf16.f32 "
        "{%0,%1,%2,%3}, {%4,%5,%6,%7}, {%8,%9}, {%0,%1,%2,%3};"
        : "+f"(c[0]), "+f"(c[1]), "+f"(c[2]), "+f"(c[3])
        : "r"(a[0]), "r"(a[1]), "r"(a[2]), "r"(a[3]), "r"(b0), "r"(b1));
}
static __device__ __forceinline__ void cpasync16(uint32_t dst, const void* src) {
    asm volatile("cp.async.cg.shared.global [%0], [%1], 16;" :: "r"(dst), "l"(src) : "memory");
}
static __device__ __forceinline__ void pksplit(float a, float b, uint32_t& hi, uint32_t& lo) {
    __nv_bfloat16 ah, al, bh, bl;
    split2(a, ah, al);
    split2(b, bh, bl);
    __nv_bfloat16 hp[2] = {ah, bh}, lp[2] = {al, bl};
    hi = *(uint32_t*)hp;
    lo = *(uint32_t*)lp;
}

// ---------------- merged weight conversion (all 4 weight groups, one launch) ----------------
#define CQ_  ((long)L_*3*D_*D_)       // qkv
#define CP_  ((long)L_*D_*D_)         // proj
#define C1_  ((long)L_*FF_*D_)        // w1
#define C2_  ((long)L_*D_*FF_)        // w2
__global__ void convall_k(const float* __restrict__ Wq, const float* __restrict__ Wk,
                          const float* __restrict__ Wv, const float* __restrict__ Wproj,
                          const float* __restrict__ W1, const float* __restrict__ W2,
                          __nv_bfloat16* __restrict__ qh, __nv_bfloat16* __restrict__ ql,
                          __nv_bfloat16* __restrict__ ph, __nv_bfloat16* __restrict__ pl,
                          __nv_bfloat16* __restrict__ o1h, __nv_bfloat16* __restrict__ o1l,
                          __nv_bfloat16* __restrict__ o2h, __nv_bfloat16* __restrict__ o2l) {
    long gi = (long)blockIdx.x * blockDim.x + threadIdx.x;
    if (gi < CQ_) {
        long i = gi;
        int k = (int)(i % D_);
        long t = i / D_;
        int n = (int)(t % (3 * D_));
        int l = (int)(t / (3 * D_));
        const float* W; int cc;
        if (n < D_)          { W = Wq; cc = n; }
        else if (n < 2 * D_) { W = Wk; cc = n - D_; }
        else                 { W = Wv; cc = n - 2 * D_; }
        int h = cc / HS_, e = cc % HS_;
        split2(W[(((long)l * H_ + h) * D_ + k) * HS_ + e], qh[i], ql[i]);
        return;
    }
    gi -= CQ_;
    if (gi < CP_) {   // proj: [L][K=D][N=D] -> [L][N][K]
        long i = gi;
        int k = (int)(i % D_);
        long t = i / D_;
        int n = (int)(t % D_);
        int l = (int)(t / D_);
        split2(Wproj[((long)l * D_ + k) * D_ + n], ph[i], pl[i]);
        return;
    }
    gi -= CP_;
    if (gi < C1_) {   // w1: [L][K=D][N=FF] -> [L][N=FF][K=D]
        long i = gi;
        int k = (int)(i % D_);
        long t = i / D_;
        int n = (int)(t % FF_);
        int l = (int)(t / FF_);
        split2(W1[((long)l * D_ + k) * FF_ + n], o1h[i], o1l[i]);
        return;
    }
    gi -= C1_;
    if (gi < C2_) {   // w2: [L][K=FF][N=D] -> [L][N=D][K=FF]
        long i = gi;
        int k = (int)(i % FF_);
        long t = i / FF_;
        int n = (int)(t % D_);
        int l = (int)(t / D_);
        split2(W2[((long)l * FF_ + k) * D_ + n], o2h[i], o2l[i]);
    }
}

// ---------------- layernorm: warp per row; optional fused embedding ----------------
// If idx != 0: x[row] is first computed as tok[idx[row]] + pos[row%T] and stored.
__global__ void ln_k(const float* __restrict__ x, float* __restrict__ y,
                     __nv_bfloat16* __restrict__ yh, __nv_bfloat16* __restrict__ yl,
                     const float* __restrict__ g, const float* __restrict__ b,
                     const int* __restrict__ idx, const float* __restrict__ tok,
                     const float* __restrict__ pos, float* __restrict__ xout) {
    int row = blockIdx.x * 8 + (threadIdx.x >> 5);
    int lane = threadIdx.x & 31;
    float v[12];
    float s = 0.f, s2 = 0.f;
    if (idx) {
        const float* tr = tok + (long)idx[row] * D_;
        const float* pr = pos + (long)(row % T_) * D_;
        #pragma unroll
        for (int i = 0; i < 12; i++) {
            int d = lane + i * 32;
            v[i] = tr[d] + pr[d];
            xout[(long)row * D_ + d] = v[i];
            s += v[i]; s2 += v[i] * v[i];
        }
    } else {
        const float* xr = x + (long)row * D_;
        #pragma unroll
        for (int i = 0; i < 12; i++) {
            v[i] = xr[lane + i * 32];
            s += v[i]; s2 += v[i] * v[i];
        }
    }
    #pragma unroll
    for (int o = 16; o; o >>= 1) {
        s  += __shfl_xor_sync(0xffffffffu, s,  o);
        s2 += __shfl_xor_sync(0xffffffffu, s2, o);
    }
    float mean = s * (1.f / D_);
    float var  = s2 * (1.f / D_) - mean * mean;
    float inv  = rsqrtf(var + 1e-5f);
    #pragma unroll
    for (int i = 0; i < 12; i++) {
        int d = lane + i * 32;
        float o = (v[i] - mean) * inv * g[d] + b[d];
        if (y) y[(long)row * D_ + d] = o;
        if (yh) split2(o, yh[(long)row * D_ + d], yl[(long)row * D_ + d]);
    }
}

// ---------------- mma.sync split-bf16 GEMM (templated on BM) ----------------
#define GSTRIDE 40
template<int BM>
__global__ void __launch_bounds__(128)
gemm_bf16_k(const __nv_bfloat16* __restrict__ Ah, const __nv_bfloat16* __restrict__ Al,
            const __nv_bfloat16* __restrict__ Bh, const __nv_bfloat16* __restrict__ Bl,
            const float* __restrict__ bias, const float* __restrict__ Cin,
            float* __restrict__ C,
            __nv_bfloat16* __restrict__ Oh, __nv_bfloat16* __restrict__ Ol,
            int N, int K, int relu) {
    constexpr int MF = BM / 32;
    constexpr int AT = BM * GSTRIDE;
    constexpr int BT = 128 * GSTRIDE;
    constexpr int BUF = 2 * AT + 2 * BT;
    extern __shared__ __align__(16) char smem[];
    uint32_t sb = s2u(smem);
    int tid = threadIdx.x, wid = tid >> 5, lane = tid & 31;
    int wm = wid >> 1, wn = wid & 1;
    int m0 = blockIdx.y * BM, n0 = blockIdx.x * 128;

    float acc[MF][8][4];
    #pragma unroll
    for (int i = 0; i < MF; i++)
        #pragma unroll
        for (int j = 0; j < 8; j++)
            #pragma unroll
            for (int q = 0; q < 4; q++) acc[i][j][q] = 0.f;

    int sel  = lane >> 3;
    int arow = (lane & 7) + ((sel & 1) << 3);
    int acol = (sel >> 1) << 3;
    int brow = (lane & 7) + ((sel >> 1) << 3);
    int bcol = (sel & 1) << 3;

    const int nch = K >> 5;

    #define ISSUE(ch, buf) do { \
        int kc = (ch) * 32; \
        const __nv_bfloat16* srcs[4] = {Ah, Al, Bh, Bl}; \
        const int offs[4] = {0, AT, 2 * AT, 2 * AT + BT}; \
        _Pragma("unroll") \
        for (int tt = 0; tt < 4; tt++) { \
            const __nv_bfloat16* sp = srcs[tt]; \
            int rb = (tt < 2) ? m0 : n0; \
            int rows = (tt < 2) ? BM : 128; \
            uint32_t db = sb + ((buf) * BUF + offs[tt]) * 2; \
            _Pragma("unroll") \
            for (int i = tid; i < rows * 4; i += 128) { \
                int r = i >> 2, c = (i & 3) * 8; \
                cpasync16(db + (r * GSTRIDE + c) * 2, sp + (long)(rb + r) * K + kc + c); \
            } \
        } \
        asm volatile("cp.async.commit_group;" ::: "memory"); \
    } while (0)

    ISSUE(0, 0);

    for (int ch = 0; ch < nch; ch++) {
        if (ch + 1 < nch) {
            ISSUE(ch + 1, (ch + 1) & 1);
            asm volatile("cp.async.wait_group 1;" ::: "memory");
        } else {
            asm volatile("cp.async.wait_group 0;" ::: "memory");
        }
        __syncthreads();

        uint32_t base = sb + ((ch & 1) * BUF) * 2;
        uint32_t tAh = base;
        uint32_t tAl = base + AT * 2;
        uint32_t tBh = base + 2 * AT * 2;
        uint32_t tBl = base + (2 * AT + BT) * 2;

        #pragma unroll
        for (int ks = 0; ks < 2; ks++) {
            int k0 = ks * 16;
            uint32_t ahf[MF][4], alf[MF][4];
            #pragma unroll
            for (int mf = 0; mf < MF; mf++) {
                uint32_t off = ((wm * (BM / 2) + mf * 16 + arow) * GSTRIDE + k0 + acol) * 2;
                ldmx4(ahf[mf], tAh + off);
                ldmx4(alf[mf], tAl + off);
            }
            uint32_t bhf[4][4], blf[4][4];
            #pragma unroll
            for (int ng = 0; ng < 4; ng++) {
                uint32_t off = ((wn * 64 + ng * 16 + brow) * GSTRIDE + k0 + bcol) * 2;
                ldmx4(bhf[ng], tBh + off);
                ldmx4(blf[ng], tBl + off);
            }
            #pragma unroll
            for (int mf = 0; mf < MF; mf++) {
                #pragma unroll
                for (int ng = 0; ng < 4; ng++) {
                    mma16816(acc[mf][ng * 2],     ahf[mf], bhf[ng][0], bhf[ng][1]);
                    mma16816(acc[mf][ng * 2 + 1], ahf[mf], bhf[ng][2], bhf[ng][3]);
                    mma16816(acc[mf][ng * 2],     ahf[mf], blf[ng][0], blf[ng][1]);
                    mma16816(acc[mf][ng * 2 + 1], ahf[mf], blf[ng][2], blf[ng][3]);
                    mma16816(acc[mf][ng * 2],     alf[mf], bhf[ng][0], bhf[ng][1]);
                    mma16816(acc[mf][ng * 2 + 1], alf[mf], bhf[ng][2], bhf[ng][3]);
                }
            }
        }
        __syncthreads();
    }

    int tr = lane >> 2, tc = (lane & 3) * 2;
    #pragma unroll
    for (int mf = 0; mf < MF; mf++) {
        #pragma unroll
        for (int half = 0; half < 2; half++) {
            long row = m0 + wm * (BM / 2) + mf * 16 + tr + half * 8;
            #pragma unroll
            for (int nf = 0; nf < 8; nf++) {
                int col = n0 + wn * 64 + nf * 8 + tc;
                float v0 = acc[mf][nf][half * 2 + 0];
                float v1 = acc[mf][nf][half * 2 + 1];
                if (bias) { v0 += bias[col]; v1 += bias[col + 1]; }
                if (Cin) {
                    float2 ci = *(const float2*)(Cin + row * (long)N + col);
                    v0 += ci.x; v1 += ci.y;
                }
                if (relu) { v0 = fmaxf(v0, 0.f); v1 = fmaxf(v1, 0.f); }
                if (C) *(float2*)(C + row * (long)N + col) = make_float2(v0, v1);
                if (Oh) {
                    uint32_t hp, lp;
                    pksplit(v0, v1, hp, lp);
                    *(uint32_t*)(Oh + row * (long)N + col) = hp;
                    *(uint32_t*)(Ol + row * (long)N + col) = lp;
                }
            }
        }
    }
}

// ---------------- small-N fp32 GEMM (head, N=65) ----------------
__global__ void gemm_k(const float* __restrict__ A, const float* __restrict__ Bw,
                       const float* __restrict__ bias, float* __restrict__ C,
                       int N, int K) {
    __shared__ float As[8][128];
    __shared__ float Bs[8][128];
    int tid = threadIdx.x;
    int m0 = blockIdx.y * 128, n0 = blockIdx.x * 128;
    int arow = tid >> 1, ac4 = (tid & 1) * 4;
    int brow = tid >> 5, bcol = (tid & 31) * 4;
    int ty = tid >> 4, tx = tid & 15;

    float acc[8][8];
    #pragma unroll
    for (int i = 0; i < 8; i++)
        #pragma unroll
        for (int j = 0; j < 8; j++) acc[i][j] = 0.f;

    const float* Aptr = A + (long)(m0 + arow) * K + ac4;

    for (int kt = 0; kt < K; kt += 8) {
        float4 av = *(const float4*)(Aptr + kt);
        As[ac4 + 0][arow] = av.x; As[ac4 + 1][arow] = av.y;
        As[ac4 + 2][arow] = av.z; As[ac4 + 3][arow] = av.w;

        int col = n0 + bcol;
        const float* bp = Bw + (long)(kt + brow) * N;
        float4 bv;
        bv.x = (col + 0 < N) ? bp[col + 0] : 0.f;
        bv.y = (col + 1 < N) ? bp[col + 1] : 0.f;
        bv.z = (col + 2 < N) ? bp[col + 2] : 0.f;
        bv.w = (col + 3 < N) ? bp[col + 3] : 0.f;
        *(float4*)&Bs[brow][bcol] = bv;
        __syncthreads();

        #pragma unroll
        for (int kk = 0; kk < 8; kk++) {
            float a[8], bb[8];
            *(float4*)&a[0]  = *(const float4*)&As[kk][ty * 8];
            *(float4*)&a[4]  = *(const float4*)&As[kk][ty * 8 + 4];
            *(float4*)&bb[0] = *(const float4*)&Bs[kk][tx * 8];
            *(float4*)&bb[4] = *(const float4*)&Bs[kk][tx * 8 + 4];
            #pragma unroll
            for (int i = 0; i < 8; i++)
                #pragma unroll
                for (int j = 0; j < 8; j++) acc[i][j] += a[i] * bb[j];
        }
        __syncthreads();
    }

    #pragma unroll
    for (int i = 0; i < 8; i++) {
        long row = m0 + ty * 8 + i;
        float* crow = C + row * (long)N;
        #pragma unroll
        for (int j = 0; j < 8; j++) {
            int col = n0 + tx * 8 + j;
            if (col < N) crow[col] = acc[i][j] + (bias ? bias[col] : 0.f);
        }
    }
}

// ---------------- tensor-core flash attention, 64-key chunks ----------------
#define ASTRIDE 72
#define AQTILE  (128*ASTRIDE)
#define AKTILE  (64*ASTRIDE)
__global__ void __launch_bounds__(256, 2)
fattn_k(const __nv_bfloat16* __restrict__ qkvh, const __nv_bfloat16* __restrict__ qkvl,
        __nv_bfloat16* __restrict__ oh, __nv_bfloat16* __restrict__ ol) {
    extern __shared__ __align__(16) char sma[];
    uint32_t sb = s2u(sma);
    __nv_bfloat16* tiles = (__nv_bfloat16*)sma;
    const uint32_t oQh = 0, oQl = AQTILE, oKh = 2 * AQTILE, oKl = 2 * AQTILE + AKTILE,
                   oVh = 2 * AQTILE + 2 * AKTILE, oVl = 2 * AQTILE + 3 * AKTILE;

    int bh = blockIdx.x;
    int b = bh / H_, h = bh % H_;
    int qb = blockIdx.y;
    int tid = threadIdx.x, wid = tid >> 5, lane = tid & 31;
    const __nv_bfloat16* baseh = qkvh + (long)b * T_ * 3 * D_;
    const __nv_bfloat16* basel = qkvl + (long)b * T_ * 3 * D_;
    const float scale = 0.05103103630798288f;  // 384^-0.5

    #define LOADBF(ROWS, trow0, coloff, dsth, dstl) do { \
        _Pragma("unroll") \
        for (int it = 0; it < (ROWS) / 32; it++) { \
            int id = tid + it * 256; \
            int r = id >> 3, c8 = (id & 7) * 8; \
            long src = (long)((trow0) + r) * (3 * D_) + (coloff) + c8; \
            *(uint4*)(tiles + (dsth) + r * ASTRIDE + c8) = *(const uint4*)(baseh + src); \
            *(uint4*)(tiles + (dstl) + r * ASTRIDE + c8) = *(const uint4*)(basel + src); \
        } \
    } while (0)

    LOADBF(128, qb * 128, h * HS_, oQh, oQl);
    LOADBF(64, 0, D_ + h * HS_, oKh, oKl);
    LOADBF(64, 0, 2 * D_ + h * HS_, oVh, oVl);
    __syncthreads();

    int sel  = lane >> 3;
    int arow = (lane & 7) + ((sel & 1) << 3);
    int acol = (sel >> 1) << 3;
    int brow = (lane & 7) + ((sel >> 1) << 3);
    int bcol = (sel & 1) << 3;
    int vrow = (lane & 7) + (((lane >> 3) & 1) << 3);
    int vcol = ((lane >> 4) & 1) << 3;

    uint32_t qfh[4][4], qfl[4][4];
    #pragma unroll
    for (int ks = 0; ks < 4; ks++) {
        uint32_t off = ((wid * 16 + arow) * ASTRIDE + ks * 16 + acol) * 2;
        ldmx4(qfh[ks], sb + oQh * 2 + off);
        ldmx4(qfl[ks], sb + oQl * 2 + off);
    }

    float So[8][4];
    #pragma unroll
    for (int a = 0; a < 8; a++)
        #pragma unroll
        for (int j = 0; j < 4; j++) So[a][j] = 0.f;
    float mrow0 = -1e30f, mrow1 = -1e30f, lrow0 = 0.f, lrow1 = 0.f;

    const int rg0 = qb * 128 + wid * 16 + (lane >> 2);
    const int ccol = (lane & 3) * 2;
    const int nch = 2 * (qb + 1);

    for (int ch = 0; ch < nch; ch++) {
        if (ch) {
            __syncthreads();
            LOADBF(64, ch * 64, D_ + h * HS_, oKh, oKl);
            LOADBF(64, ch * 64, 2 * D_ + h * HS_, oVh, oVl);
            __syncthreads();
        }
        float sa[8][4];
        #pragma unroll
        for (int ni = 0; ni < 8; ni++)
            #pragma unroll
            for (int j = 0; j < 4; j++) sa[ni][j] = 0.f;
        #pragma unroll
        for (int ks = 0; ks < 4; ks++) {
            #pragma unroll
            for (int ng = 0; ng < 4; ng++) {
                uint32_t off = ((ng * 16 + brow) * ASTRIDE + ks * 16 + bcol) * 2;
                uint32_t kh4[4], kl4[4];
                ldmx4(kh4, sb + oKh * 2 + off);
                ldmx4(kl4, sb + oKl * 2 + off);
                mma16816(sa[ng * 2],     qfh[ks], kh4[0], kh4[1]);
                mma16816(sa[ng * 2 + 1], qfh[ks], kh4[2], kh4[3]);
                mma16816(sa[ng * 2],     qfh[ks], kl4[0], kl4[1]);
                mma16816(sa[ng * 2 + 1], qfh[ks], kl4[2], kl4[3]);
                mma16816(sa[ng * 2],     qfl[ks], kh4[0], kh4[1]);
                mma16816(sa[ng * 2 + 1], qfl[ks], kh4[2], kh4[3]);
            }
        }
        #pragma unroll
        for (int ni = 0; ni < 8; ni++) {
            #pragma unroll
            for (int j = 0; j < 4; j++) {
                float s = sa[ni][j] * scale;
                int key = ch * 64 + ni * 8 + ccol + (j & 1);
                int qr  = rg0 + ((j >> 1) << 3);
                if (key > qr) s = -1e30f;
                sa[ni][j] = s;
            }
        }
        float mx0 = -1e30f, mx1 = -1e30f;
        #pragma unroll
        for (int ni = 0; ni < 8; ni++) {
            mx0 = fmaxf(mx0, fmaxf(sa[ni][0], sa[ni][1]));
            mx1 = fmaxf(mx1, fmaxf(sa[ni][2], sa[ni][3]));
        }
        mx0 = fmaxf(mx0, __shfl_xor_sync(0xffffffffu, mx0, 1));
        mx0 = fmaxf(mx0, __shfl_xor_sync(0xffffffffu, mx0, 2));
        mx1 = fmaxf(mx1, __shfl_xor_sync(0xffffffffu, mx1, 1));
        mx1 = fmaxf(mx1, __shfl_xor_sync(0xffffffffu, mx1, 2));
        float mn0 = fmaxf(mrow0, mx0), mn1 = fmaxf(mrow1, mx1);
        float c0 = __expf(mrow0 - mn0), c1 = __expf(mrow1 - mn1);
        mrow0 = mn0; mrow1 = mn1;
        float s0 = 0.f, s1 = 0.f;
        #pragma unroll
        for (int ni = 0; ni < 8; ni++) {
            sa[ni][0] = __expf(sa[ni][0] - mn0);
            sa[ni][1] = __expf(sa[ni][1] - mn0);
            sa[ni][2] = __expf(sa[ni][2] - mn1);
            sa[ni][3] = __expf(sa[ni][3] - mn1);
            s0 += sa[ni][0] + sa[ni][1];
            s1 += sa[ni][2] + sa[ni][3];
        }
        s0 += __shfl_xor_sync(0xffffffffu, s0, 1);
        s0 += __shfl_xor_sync(0xffffffffu, s0, 2);
        s1 += __shfl_xor_sync(0xffffffffu, s1, 1);
        s1 += __shfl_xor_sync(0xffffffffu, s1, 2);
        lrow0 = lrow0 * c0 + s0;
        lrow1 = lrow1 * c1 + s1;
        #pragma unroll
        for (int a = 0; a < 8; a++) {
            So[a][0] *= c0; So[a][1] *= c0;
            So[a][2] *= c1; So[a][3] *= c1;
        }
        #pragma unroll
        for (int ks = 0; ks < 4; ks++) {
            uint32_t pfh[4], pfl[4];
            pksplit(sa[2 * ks][0],     sa[2 * ks][1],     pfh[0], pfl[0]);
            pksplit(sa[2 * ks][2],     sa[2 * ks][3],     pfh[1], pfl[1]);
            pksplit(sa[2 * ks + 1][0], sa[2 * ks + 1][1], pfh[2], pfl[2]);
            pksplit(sa[2 * ks + 1][2], sa[2 * ks + 1][3], pfh[3], pfl[3]);
            #pragma unroll
            for (int np = 0; np < 4; np++) {
                uint32_t voff = ((ks * 16 + vrow) * ASTRIDE + np * 16 + vcol) * 2;
                uint32_t vh4[4], vl4[4];
                ldmx4t(vh4, sb + oVh * 2 + voff);
                ldmx4t(vl4, sb + oVl * 2 + voff);
                mma16816(So[np * 2],     pfh, vh4[0], vh4[1]);
                mma16816(So[np * 2 + 1], pfh, vh4[2], vh4[3]);
                mma16816(So[np * 2],     pfh, vl4[0], vl4[1]);
                mma16816(So[np * 2 + 1], pfh, vl4[2], vl4[3]);
                mma16816(So[np * 2],     pfl, vh4[0], vh4[1]);
                mma16816(So[np * 2 + 1], pfl, vh4[2], vh4[3]);
            }
        }
    }

    float rl0 = 1.f / lrow0, rl1 = 1.f / lrow1;
    #pragma unroll
    for (int a = 0; a < 8; a++) {
        int col = h * HS_ + a * 8 + ccol;
        long row0 = (long)b * T_ + rg0;
        long row1 = row0 + 8;
        uint32_t hp, lp;
        pksplit(So[a][0] * rl0, So[a][1] * rl0, hp, lp);
        *(uint32_t*)(oh + row0 * D_ + col) = hp;
        *(uint32_t*)(ol + row0 * D_ + col) = lp;
        pksplit(So[a][2] * rl1, So[a][3] * rl1, hp, lp);
        *(uint32_t*)(oh + row1 * D_ + col) = hp;
        *(uint32_t*)(ol + row1 * D_ + col) = lp;
    }
}

// ---------------- loss ----------------
__global__ void loss_k(const float* __restrict__ logits, const int* __restrict__ targets,
                       float* __restrict__ part) {
    int gwarp = (blockIdx.x * blockDim.x + threadIdx.x) >> 5;
    int lane = threadIdx.x & 31;
    const float* lr = logits + (long)gwarp * V_;
    float mx = -1e30f;
    for (int c = lane; c < V_; c += 32) mx = fmaxf(mx, lr[c]);
    #pragma unroll
    for (int o = 16; o; o >>= 1) mx = fmaxf(mx, __shfl_xor_sync(0xffffffffu, mx, o));
    float se = 0.f;
    for (int c = lane; c < V_; c += 32) se += expf(lr[c] - mx);
    #pragma unroll
    for (int o = 16; o; o >>= 1) se += __shfl_xor_sync(0xffffffffu, se, o);
    float li = (mx + logf(se)) - lr[targets[gwarp]];
    __shared__ float ws[8];
    if (lane == 0) ws[threadIdx.x >> 5] = li;
    __syncthreads();
    if (threadIdx.x == 0) {
        float s = 0.f;
        #pragma unroll
        for (int i = 0; i < 8; i++) s += ws[i];
        part[blockIdx.x] = s;
    }
}

__global__ void finalize_k(float* out, long out_size, const float* __restrict__ part) {
    float v = 0.f;
    for (int i = threadIdx.x; i < 2048; i += 256) v += part[i];
    #pragma unroll
    for (int o = 16; o; o >>= 1) v += __shfl_xor_sync(0xffffffffu, v, o);
    __shared__ float sm[8];
    if ((threadIdx.x & 31) == 0) sm[threadIdx.x >> 5] = v;
    __syncthreads();
    if (threadIdx.x == 0) {
        float s = 0.f;
        #pragma unroll
        for (int i = 0; i < 8; i++) s += sm[i];
        float loss = s / (float)M_;
        const long btv = (long)M_ * V_;
        if (out_size > btv)       out[btv] = loss;
        else if (out_size == 1)   out[0]   = loss;
    }
}

// ---------------- driver ----------------
extern "C" void kernel_launch(void* const* d_in, const int* in_sizes, int n_in,
                              void* d_out, int out_size) {
    const int*   idx     = (const int*)d_in[0];
    const int*   targets = (const int*)d_in[1];
    const float* tok     = (const float*)d_in[2];
    const float* pos     = (const float*)d_in[3];
    const float* Wq      = (const float*)d_in[4];
    const float* Wk      = (const float*)d_in[5];
    const float* Wv      = (const float*)d_in[6];
    const float* Wproj   = (const float*)d_in[7];
    const float* bproj   = (const float*)d_in[8];
    const float* W1      = (const float*)d_in[9];
    const float* b1      = (const float*)d_in[10];
    const float* W2      = (const float*)d_in[11];
    const float* b2      = (const float*)d_in[12];
    const float* ln1g    = (const float*)d_in[13];
    const float* ln1b    = (const float*)d_in[14];
    const float* lnfg    = (const float*)d_in[15];
    const float* lnfb    = (const float*)d_in[16];
    const float* Whead   = (const float*)d_in[17];
    const float* bhead   = (const float*)d_in[18];
    float* out = (float*)d_out;

    float *x, *y, *lgts, *part;
    __nv_bfloat16 *qkvh, *qkvl, *yh, *yl, *oh, *ol, *h1h, *h1l;
    __nv_bfloat16 *wqh, *wql, *wph, *wpl, *w1h, *w1l, *w2h, *w2l;
    cudaGetSymbolAddress((void**)&x,    g_x);
    cudaGetSymbolAddress((void**)&y,    g_y);
    cudaGetSymbolAddress((void**)&lgts, g_logits);
    cudaGetSymbolAddress((void**)&part, g_losspart);
    cudaGetSymbolAddress((void**)&qkvh, g_qkvh);
    cudaGetSymbolAddress((void**)&qkvl, g_qkvl);
    cudaGetSymbolAddress((void**)&yh,   g_yh);
    cudaGetSymbolAddress((void**)&yl,   g_yl);
    cudaGetSymbolAddress((void**)&oh,   g_oh);
    cudaGetSymbolAddress((void**)&ol,   g_ol);
    cudaGetSymbolAddress((void**)&h1h,  g_h1h);
    cudaGetSymbolAddress((void**)&h1l,  g_h1l);
    cudaGetSymbolAddress((void**)&wqh,  g_wqkvh);
    cudaGetSymbolAddress((void**)&wql,  g_wqkvl);
    cudaGetSymbolAddress((void**)&wph,  g_wprojh);
    cudaGetSymbolAddress((void**)&wpl,  g_wprojl);
    cudaGetSymbolAddress((void**)&w1h,  g_w1h);
    cudaGetSymbolAddress((void**)&w1l,  g_w1l);
    cudaGetSymbolAddress((void**)&w2h,  g_w2h);
    cudaGetSymbolAddress((void**)&w2l,  g_w2l);

    const int attn_smem = (2 * AQTILE + 4 * AKTILE) * 2;   // 73728 B
    cudaFuncSetAttribute(fattn_k, cudaFuncAttributeMaxDynamicSharedMemorySize, attn_smem);
    const int gsmem128 = 2 * (2 * 128 * GSTRIDE + 2 * 128 * GSTRIDE) * 2;  // 81920
    const int gsmem64  = 2 * (2 * 64 * GSTRIDE + 2 * 128 * GSTRIDE) * 2;   // 61440
    cudaFuncSetAttribute(gemm_bf16_k<128>, cudaFuncAttributeMaxDynamicSharedMemorySize, gsmem128);
    cudaFuncSetAttribute(gemm_bf16_k<64>,  cudaFuncAttributeMaxDynamicSharedMemorySize, gsmem64);

    const long btv = (long)M_ * V_;
    float* logits = ((long)out_size >= btv) ? out : lgts;

    {
        long total = CQ_ + CP_ + C1_ + C2_;
        convall_k<<<(int)((total + 255) / 256), 256>>>(Wq, Wk, Wv, Wproj, W1, W2,
            wqh, wql, wph, wpl, w1h, w1l, w2h, w2l);
    }

    for (int l = 0; l < L_; l++) {
        // first LN of layer 0 also computes the embedding into x
        ln_k<<<M_ / 8, 256>>>(x, (float*)0, yh, yl,
                              ln1g + (long)l * D_, ln1b + (long)l * D_,
                              (l == 0) ? idx : (const int*)0, tok, pos, x);
        { dim3 g(9, 128);
          gemm_bf16_k<128><<<g, 128, gsmem128>>>(yh, yl,
              wqh + (long)l * 3 * D_ * D_, wql + (long)l * 3 * D_ * D_,
              (const float*)0, (const float*)0, (float*)0,
              qkvh, qkvl, 3 * D_, D_, 0); }
        { dim3 ga(B_ * H_, 2);
          fattn_k<<<ga, 256, attn_smem>>>(qkvh, qkvl, oh, ol); }
        { dim3 g(3, 256);
          gemm_bf16_k<64><<<g, 128, gsmem64>>>(oh, ol,
              wph + (long)l * D_ * D_, wpl + (long)l * D_ * D_,
              bproj + (long)l * D_, x, x,
              (__nv_bfloat16*)0, (__nv_bfloat16*)0, D_, D_, 0); }
        ln_k<<<M_ / 8, 256>>>(x, (float*)0, yh, yl,
                              ln1g + (long)l * D_, ln1b + (long)l * D_,
                              (const int*)0, tok, pos, (float*)0);
        { dim3 g(12, 128);
          gemm_bf16_k<128><<<g, 128, gsmem128>>>(yh, yl,
              w1h + (long)l * FF_ * D_, w1l + (long)l * FF_ * D_,
              b1 + (long)l * FF_, (const float*)0, (float*)0,
              h1h, h1l, FF_, D_, 1); }
        { dim3 g(3, 256);
          gemm_bf16_k<64><<<g, 128, gsmem64>>>(h1h, h1l,
              w2h + (long)l * D_ * FF_, w2l + (long)l * D_ * FF_,
              b2 + (long)l * D_, x, x,
              (__nv_bfloat16*)0, (__nv_bfloat16*)0, D_, FF_, 0); }
    }

    ln_k<<<M_ / 8, 256>>>(x, y, (__nv_bfloat16*)0, (__nv_bfloat16*)0, lnfg, lnfb,
                          (const int*)0, tok, pos, (float*)0);
    { dim3 g(1, 128); gemm_k<<<g, 256>>>(y, Whead, bhead, logits, V_, D_); }
    loss_k<<<2048, 256>>>(logits, targets, part);
    finalize_k<<<1, 256>>>(out, (long)out_size, part);
}